// round 1
// baseline (speedup 1.0000x reference)
#include <cuda_runtime.h>
#include <cuda_bf16.h>
#include <math.h>

// Problem dims
#define LL 16
#define TT 2048
#define DD 2048
#define RR 128
#define KCAP 1024   // selected tokens per layer; TT-KCAP = 1024 unselected

typedef unsigned long long u64;

// ---------------- scratch (device globals; no allocation allowed) ------------
__device__ float g_H[(size_t)LL * TT * RR];      // router hidden, 16 MB
__device__ float g_probs[LL * TT];
__device__ int   g_sel [LL * KCAP];              // selected token ids (slot = rank)
__device__ int   g_idx0[LL * (TT - KCAP)];       // unselected token ids (slot = rank-KCAP)

// ---------------- packed f32x2 helpers (Blackwell FFMA2 path) ----------------
__device__ __forceinline__ u64 pack2(float x, float y) {
    u64 r; asm("mov.b64 %0, {%1, %2};" : "=l"(r) : "f"(x), "f"(y)); return r;
}
__device__ __forceinline__ u64 fma2(u64 a, u64 b, u64 c) {
    u64 d; asm("fma.rn.f32x2 %0, %1, %2, %3;" : "=l"(d) : "l"(a), "l"(b), "l"(c)); return d;
}
__device__ __forceinline__ float2 unpack2(u64 v) {
    float2 f; asm("mov.b64 {%0, %1}, %2;" : "=f"(f.x), "=f"(f.y) : "l"(v)); return f;
}

// ---------------- GEMM tile config ----------------
#define BM 128
#define BN 128
#define BK 16
// 256 threads, each computes an 8x8 micro-tile (held as 8x4 f32x2 pairs)

// =====================================================================
// Kernel 1: router GEMM1.  H[l,t,r] = relu(hidden[l,t,:] @ W_r1[l,:,r] + b_r1[l,r])
// grid (1, T/BM, L), block 256
// =====================================================================
__global__ __launch_bounds__(256, 2)
void router_gemm_kernel(const float* __restrict__ hidden,
                        const float* __restrict__ W_r1,
                        const float* __restrict__ b_r1) {
    __shared__ float As[BK][BM];
    __shared__ float Bs[BK][BN];

    const int l   = blockIdx.z;
    const int mb  = blockIdx.y;
    const int tid = threadIdx.x;

    const float* A = hidden + (size_t)l * TT * DD + (size_t)(mb * BM) * DD;
    const float* B = W_r1   + (size_t)l * DD * RR;          // [D][R], ldb = R = 128 = BN

    const int arow = tid >> 2;            // 0..63  (and +64)
    const int acol = (tid & 3) * 4;       // 0,4,8,12
    const int brow = tid >> 5;            // 0..7   (and +8)
    const int bcol = (tid & 31) * 4;      // 0..124

    const int tx = tid & 15, ty = tid >> 4;

    u64 acc[8][4];
    #pragma unroll
    for (int i = 0; i < 8; i++)
        #pragma unroll
        for (int j = 0; j < 4; j++) acc[i][j] = 0ull;

    for (int kt = 0; kt < DD; kt += BK) {
        float4 a0 = *(const float4*)(A + (size_t)arow        * DD + kt + acol);
        float4 a1 = *(const float4*)(A + (size_t)(arow + 64) * DD + kt + acol);
        float4 b0 = *(const float4*)(B + (size_t)(kt + brow)     * RR + bcol);
        float4 b1 = *(const float4*)(B + (size_t)(kt + brow + 8) * RR + bcol);
        __syncthreads();
        As[acol + 0][arow] = a0.x;  As[acol + 1][arow] = a0.y;
        As[acol + 2][arow] = a0.z;  As[acol + 3][arow] = a0.w;
        As[acol + 0][arow + 64] = a1.x;  As[acol + 1][arow + 64] = a1.y;
        As[acol + 2][arow + 64] = a1.z;  As[acol + 3][arow + 64] = a1.w;
        *(float4*)&Bs[brow][bcol]     = b0;
        *(float4*)&Bs[brow + 8][bcol] = b1;
        __syncthreads();
        #pragma unroll
        for (int k = 0; k < BK; k++) {
            float4 av0 = *(const float4*)&As[k][ty * 8];
            float4 av1 = *(const float4*)&As[k][ty * 8 + 4];
            u64 aa[8];
            aa[0] = pack2(av0.x, av0.x); aa[1] = pack2(av0.y, av0.y);
            aa[2] = pack2(av0.z, av0.z); aa[3] = pack2(av0.w, av0.w);
            aa[4] = pack2(av1.x, av1.x); aa[5] = pack2(av1.y, av1.y);
            aa[6] = pack2(av1.z, av1.z); aa[7] = pack2(av1.w, av1.w);
            const u64* bp = (const u64*)&Bs[k][tx * 8];
            u64 bb0 = bp[0], bb1 = bp[1], bb2 = bp[2], bb3 = bp[3];
            #pragma unroll
            for (int i = 0; i < 8; i++) {
                acc[i][0] = fma2(aa[i], bb0, acc[i][0]);
                acc[i][1] = fma2(aa[i], bb1, acc[i][1]);
                acc[i][2] = fma2(aa[i], bb2, acc[i][2]);
                acc[i][3] = fma2(aa[i], bb3, acc[i][3]);
            }
        }
    }

    // epilogue: +bias, relu, store H
    #pragma unroll
    for (int i = 0; i < 8; i++) {
        int t = mb * BM + ty * 8 + i;
        float* hrow = g_H + ((size_t)l * TT + t) * RR + tx * 8;
        #pragma unroll
        for (int j = 0; j < 4; j++) {
            float2 v = unpack2(acc[i][j]);
            float2 bb = *(const float2*)&b_r1[l * RR + tx * 8 + 2 * j];
            v.x = fmaxf(v.x + bb.x, 0.0f);
            v.y = fmaxf(v.y + bb.y, 0.0f);
            *(float2*)(hrow + 2 * j) = v;
        }
    }
}

// =====================================================================
// Kernel 2: logits + sigmoid. One warp per token.
// =====================================================================
__global__ void logits_kernel(const float* __restrict__ W_r2,
                              const float* __restrict__ b_r2) {
    int gw   = (blockIdx.x * blockDim.x + threadIdx.x) >> 5;
    int lane = threadIdx.x & 31;
    if (gw >= LL * TT) return;
    int l = gw >> 11;
    const float* h = g_H + (size_t)gw * RR;
    const float* w = W_r2 + l * RR;
    float s = 0.0f;
    #pragma unroll
    for (int r = lane; r < RR; r += 32) s += h[r] * w[r];
    #pragma unroll
    for (int o = 16; o; o >>= 1) s += __shfl_xor_sync(0xFFFFFFFFu, s, o);
    if (lane == 0) {
        float x = s + b_r2[l];
        g_probs[gw] = 1.0f / (1.0f + expf(-x));
    }
}

// =====================================================================
// Kernel 3: exact rank -> mask + compaction. One block per layer.
// rank_t = #{s: p_s > p_t} + #{s<t: p_s == p_t}  (matches top_k tie-break)
// =====================================================================
__global__ void rank_kernel() {
    __shared__ float sp[TT];
    int l = blockIdx.x;
    for (int t = threadIdx.x; t < TT; t += blockDim.x) sp[t] = g_probs[l * TT + t];
    __syncthreads();
    for (int t = threadIdx.x; t < TT; t += blockDim.x) {
        float pt = sp[t];
        int rank = 0;
        for (int s = 0; s < TT; s++) {
            float ps = sp[s];
            rank += (ps > pt) || (ps == pt && s < t);
        }
        if (rank < KCAP) g_sel[l * KCAP + rank] = t;
        else             g_idx0[l * KCAP + (rank - KCAP)] = t;
    }
}

// =====================================================================
// Kernel 4: selected rows: out = ((1-p)+p) * s2   (drop (1-m)*s1, |1-m|<=1.2e-7)
// grid L*KCAP blocks, 256 threads
// =====================================================================
__global__ void copy_sel_kernel(const float* __restrict__ s2,
                                float* __restrict__ out) {
    int b = blockIdx.x;
    int l = b >> 10;
    int t = g_sel[b];
    float p = g_probs[l * TT + t];
    float m = (1.0f - p) + p;
    size_t off = ((size_t)l * TT + t) * DD;
    const float4* src = (const float4*)(s2 + off);
    float4*       dst = (float4*)(out + off);
    #pragma unroll
    for (int i = threadIdx.x; i < DD / 4; i += 256) {
        float4 v = src[i];
        dst[i] = make_float4(m * v.x, m * v.y, m * v.z, m * v.w);
    }
}

// =====================================================================
// Kernel 5: main GEMM on the 1024 UNSELECTED rows per layer (m==0 exactly).
// out[l, row, :] = hidden[l,row,:] @ W_s1[l] + b_s1[l]
// grid (D/BN=16, (T-K)/BM=8, L), block 256
// =====================================================================
__global__ __launch_bounds__(256, 2)
void gemm_s1_kernel(const float* __restrict__ hidden,
                    const float* __restrict__ W_s1,
                    const float* __restrict__ b_s1,
                    float* __restrict__ out) {
    __shared__ float As[BK][BM];
    __shared__ float Bs[BK][BN];
    __shared__ int   rows[BM];

    const int l   = blockIdx.z;
    const int mb  = blockIdx.y;
    const int nb  = blockIdx.x;
    const int tid = threadIdx.x;

    if (tid < BM) rows[tid] = g_idx0[l * KCAP + mb * BM + tid];
    __syncthreads();

    const float* A  = hidden + (size_t)l * TT * DD;
    const float* Bp = W_s1   + (size_t)l * DD * DD + nb * BN;

    const int arow = tid >> 2;
    const int acol = (tid & 3) * 4;
    const int brow = tid >> 5;
    const int bcol = (tid & 31) * 4;
    const int tx = tid & 15, ty = tid >> 4;

    u64 acc[8][4];
    #pragma unroll
    for (int i = 0; i < 8; i++)
        #pragma unroll
        for (int j = 0; j < 4; j++) acc[i][j] = 0ull;

    const int r0 = rows[arow], r1 = rows[arow + 64];

    for (int kt = 0; kt < DD; kt += BK) {
        float4 a0 = *(const float4*)(A + (size_t)r0 * DD + kt + acol);
        float4 a1 = *(const float4*)(A + (size_t)r1 * DD + kt + acol);
        float4 b0 = *(const float4*)(Bp + (size_t)(kt + brow)     * DD + bcol);
        float4 b1 = *(const float4*)(Bp + (size_t)(kt + brow + 8) * DD + bcol);
        __syncthreads();
        As[acol + 0][arow] = a0.x;  As[acol + 1][arow] = a0.y;
        As[acol + 2][arow] = a0.z;  As[acol + 3][arow] = a0.w;
        As[acol + 0][arow + 64] = a1.x;  As[acol + 1][arow + 64] = a1.y;
        As[acol + 2][arow + 64] = a1.z;  As[acol + 3][arow + 64] = a1.w;
        *(float4*)&Bs[brow][bcol]     = b0;
        *(float4*)&Bs[brow + 8][bcol] = b1;
        __syncthreads();
        #pragma unroll
        for (int k = 0; k < BK; k++) {
            float4 av0 = *(const float4*)&As[k][ty * 8];
            float4 av1 = *(const float4*)&As[k][ty * 8 + 4];
            u64 aa[8];
            aa[0] = pack2(av0.x, av0.x); aa[1] = pack2(av0.y, av0.y);
            aa[2] = pack2(av0.z, av0.z); aa[3] = pack2(av0.w, av0.w);
            aa[4] = pack2(av1.x, av1.x); aa[5] = pack2(av1.y, av1.y);
            aa[6] = pack2(av1.z, av1.z); aa[7] = pack2(av1.w, av1.w);
            const u64* bp = (const u64*)&Bs[k][tx * 8];
            u64 bb0 = bp[0], bb1 = bp[1], bb2 = bp[2], bb3 = bp[3];
            #pragma unroll
            for (int i = 0; i < 8; i++) {
                acc[i][0] = fma2(aa[i], bb0, acc[i][0]);
                acc[i][1] = fma2(aa[i], bb1, acc[i][1]);
                acc[i][2] = fma2(aa[i], bb2, acc[i][2]);
                acc[i][3] = fma2(aa[i], bb3, acc[i][3]);
            }
        }
    }

    #pragma unroll
    for (int i = 0; i < 8; i++) {
        int trow = rows[ty * 8 + i];
        float* orow = out + ((size_t)l * TT + trow) * DD + nb * BN + tx * 8;
        #pragma unroll
        for (int j = 0; j < 4; j++) {
            float2 v  = unpack2(acc[i][j]);
            float2 bb = *(const float2*)&b_s1[l * DD + nb * BN + tx * 8 + 2 * j];
            v.x += bb.x; v.y += bb.y;
            *(float2*)(orow + 2 * j) = v;
        }
    }
}

// =====================================================================
extern "C" void kernel_launch(void* const* d_in, const int* in_sizes, int n_in,
                              void* d_out, int out_size) {
    const float* hidden = (const float*)d_in[0];
    const float* s2     = (const float*)d_in[1];
    const float* W_r1   = (const float*)d_in[2];
    const float* b_r1   = (const float*)d_in[3];
    const float* W_r2   = (const float*)d_in[4];
    const float* b_r2   = (const float*)d_in[5];
    const float* W_s1   = (const float*)d_in[6];
    const float* b_s1   = (const float*)d_in[7];
    float* out = (float*)d_out;

    router_gemm_kernel<<<dim3(1, TT / BM, LL), 256>>>(hidden, W_r1, b_r1);
    logits_kernel<<<(LL * TT * 32) / 256, 256>>>(W_r2, b_r2);
    rank_kernel<<<LL, 1024>>>();
    copy_sel_kernel<<<LL * KCAP, 256>>>(s2, out);
    gemm_s1_kernel<<<dim3(DD / BN, (TT - KCAP) / BM, LL), 256>>>(hidden, W_s1, b_s1, out);
}

// round 4
// speedup vs baseline: 1.4378x; 1.4378x over previous
#include <cuda_runtime.h>
#include <cuda_bf16.h>
#include <math.h>
#include <stdint.h>

// Problem dims
#define LL 16
#define TT 2048
#define DD 2048
#define RR 128
#define KCAP 1024
#define WIN 32          // boundary fixup window
#define HW (WIN / 2)

// ---------------- scratch (device globals) ----------------
__device__ float g_H[(size_t)LL * TT * RR];
__device__ float g_probs[LL * TT];
__device__ int   g_sel [LL * KCAP];
__device__ int   g_idx0[LL * KCAP];
__device__ int   g_bnd [LL * WIN];
// bf16 hi/lo split copies
__device__ __nv_bfloat16 g_Ah[(size_t)LL * TT * DD];
__device__ __nv_bfloat16 g_Al[(size_t)LL * TT * DD];
__device__ __nv_bfloat16 g_Ws1t_hi[(size_t)LL * DD * DD];   // W_s1^T [L,N,K]
__device__ __nv_bfloat16 g_Ws1t_lo[(size_t)LL * DD * DD];
__device__ __nv_bfloat16 g_Wr1t_hi[(size_t)LL * RR * DD];   // W_r1^T [L,R,K]
__device__ __nv_bfloat16 g_Wr1t_lo[(size_t)LL * RR * DD];

// ---------------- PTX helpers (baseline ISA only) ----------------
__device__ __forceinline__ uint32_t smem_u32(const void* p) {
    uint32_t a;
    asm("{ .reg .u64 t; cvta.to.shared.u64 t, %1; cvt.u32.u64 %0, t; }" : "=r"(a) : "l"(p));
    return a;
}
#define CP16(dst, src) \
    asm volatile("cp.async.cg.shared.global [%0], [%1], 16;" :: "r"(dst), "l"(src))
#define CP_COMMIT() asm volatile("cp.async.commit_group;")
#define CP_WAIT(n)  asm volatile("cp.async.wait_group %0;" :: "n"(n))

__device__ __forceinline__ void ldsm_x4(uint32_t* r, uint32_t addr) {
    asm volatile("ldmatrix.sync.aligned.m8n8.x4.shared.b16 {%0,%1,%2,%3}, [%4];"
                 : "=r"(r[0]), "=r"(r[1]), "=r"(r[2]), "=r"(r[3]) : "r"(addr));
}
__device__ __forceinline__ void mma16816(float* d, const uint32_t* a,
                                         uint32_t b0, uint32_t b1) {
    asm volatile(
        "mma.sync.aligned.m16n8k16.row.col.f32.bf16.bf16.f32 "
        "{%0,%1,%2,%3}, {%4,%5,%6,%7}, {%8,%9}, {%0,%1,%2,%3};"
        : "+f"(d[0]), "+f"(d[1]), "+f"(d[2]), "+f"(d[3])
        : "r"(a[0]), "r"(a[1]), "r"(a[2]), "r"(a[3]), "r"(b0), "r"(b1));
}

// bf16 hi/lo split of two floats, packed (y<<16)|x
__device__ __forceinline__ void split2(float x, float y, uint32_t& hi, uint32_t& lo) {
    __nv_bfloat16 hx = __float2bfloat16(x);
    __nv_bfloat16 hy = __float2bfloat16(y);
    __nv_bfloat16 lx = __float2bfloat16(x - __bfloat162float(hx));
    __nv_bfloat16 ly = __float2bfloat16(y - __bfloat162float(hy));
    hi = ((uint32_t)__bfloat16_as_ushort(hy) << 16) | __bfloat16_as_ushort(hx);
    lo = ((uint32_t)__bfloat16_as_ushort(ly) << 16) | __bfloat16_as_ushort(lx);
}

// =====================================================================
// hidden f32 -> g_Ah / g_Al bf16
// =====================================================================
__global__ void split_hidden_kernel(const float4* __restrict__ h) {
    size_t i = (size_t)blockIdx.x * blockDim.x + threadIdx.x;
    float4 v = h[i];
    uint32_t h01, l01, h23, l23;
    split2(v.x, v.y, h01, l01);
    split2(v.z, v.w, h23, l23);
    ((uint2*)g_Ah)[i] = make_uint2(h01, h23);
    ((uint2*)g_Al)[i] = make_uint2(l01, l23);
}

// =====================================================================
// W[l,k,n] f32 -> Wt_hi/lo[l,n,k] bf16
// =====================================================================
template<bool S1>
__global__ void transpose_split_kernel(const float* __restrict__ W, int K, int N) {
    __shared__ float tile[32][33];
    const int l  = blockIdx.z;
    const int k0 = blockIdx.x * 32;
    const int n0 = blockIdx.y * 32;
    const int tx = threadIdx.x, ty = threadIdx.y;
    const float* Wl = W + (size_t)l * K * N;
    #pragma unroll
    for (int r = 0; r < 4; r++)
        tile[ty + r * 8][tx] = Wl[(size_t)(k0 + ty + r * 8) * N + n0 + tx];
    __syncthreads();
    __nv_bfloat16* hiB = S1 ? g_Ws1t_hi : g_Wr1t_hi;
    __nv_bfloat16* loB = S1 ? g_Ws1t_lo : g_Wr1t_lo;
    #pragma unroll
    for (int r = 0; r < 4; r++) {
        int n = n0 + ty + r * 8;
        float v = tile[tx][ty + r * 8];
        __nv_bfloat16 h = __float2bfloat16(v);
        __nv_bfloat16 lo = __float2bfloat16(v - __bfloat162float(h));
        size_t o = ((size_t)l * N + n) * K + k0 + tx;
        hiB[o] = h;
        loB[o] = lo;
    }
}

// =====================================================================
// HMMA GEMM: C[128 x 128 tile] = A(bf16 hi/lo) @ B^T(bf16 hi/lo), 3-term split.
// grid (mtiles, Ntot/128, L), 256 threads (warps 4x2), BK=32, 2-stage cp.async.
// TO_GH: write result to device-global g_H (router) instead of Cout arg.
// =====================================================================
#define PITCH 40                    // bf16 elts per smem row (32 + 8 pad)
#define MAT_ELT (128 * PITCH)       // 5120 elts per matrix
#define MAT_B   (MAT_ELT * 2)       // 10240 bytes
#define STG_B   (4 * MAT_B)         // Ah,Al,Bh,Bl : 40960 bytes
#define NITER   (DD / 32)           // 64

template<bool GATHER, bool RELU, bool TO_GH>
__global__ __launch_bounds__(256, 1)
void hmma_gemm_kernel(const float* __restrict__ bias,
                      float* __restrict__ Cout, int Ntot) {
    extern __shared__ __align__(16) char smraw[];
    const uint32_t smb = smem_u32(smraw);

    const int tid  = threadIdx.x;
    const int lane = tid & 31;
    const int wid  = tid >> 5;
    const int warp_m = wid & 3;     // 4 warps over M (32 rows each)
    const int warp_n = wid >> 2;    // 2 warps over N (64 cols each)
    const int mb = blockIdx.x, nb = blockIdx.y, l = blockIdx.z;

    __shared__ int s_rows[128];
    if (tid < 128)
        s_rows[tid] = GATHER ? g_idx0[l * KCAP + mb * 128 + tid] : (mb * 128 + tid);
    __syncthreads();

    const __nv_bfloat16* __restrict__ AHt = g_Ah + (size_t)l * TT * DD;
    const __nv_bfloat16* __restrict__ ALt = g_Al + (size_t)l * TT * DD;
    const __nv_bfloat16* __restrict__ BHt =
        (GATHER ? g_Ws1t_hi : g_Wr1t_hi) + ((size_t)l * Ntot + nb * 128) * DD;
    const __nv_bfloat16* __restrict__ BLt =
        (GATHER ? g_Ws1t_lo : g_Wr1t_lo) + ((size_t)l * Ntot + nb * 128) * DD;

    // cp.async assignment: 512 chunks of 16B per matrix; this thread owns c0,c1
    const int c0 = tid, c1 = tid + 256;
    const int r0 = c0 >> 2, r1 = c1 >> 2;
    const int f0 = (c0 & 3) * 8, f1 = (c1 & 3) * 8;        // elt col
    const __nv_bfloat16* sA0h = AHt + (size_t)s_rows[r0] * DD + f0;
    const __nv_bfloat16* sA0l = ALt + (size_t)s_rows[r0] * DD + f0;
    const __nv_bfloat16* sA1h = AHt + (size_t)s_rows[r1] * DD + f1;
    const __nv_bfloat16* sA1l = ALt + (size_t)s_rows[r1] * DD + f1;
    const __nv_bfloat16* sB0h = BHt + (size_t)r0 * DD + f0;
    const __nv_bfloat16* sB0l = BLt + (size_t)r0 * DD + f0;
    const __nv_bfloat16* sB1h = BHt + (size_t)r1 * DD + f1;
    const __nv_bfloat16* sB1l = BLt + (size_t)r1 * DD + f1;
    const uint32_t d0 = (uint32_t)(r0 * PITCH + f0) * 2;
    const uint32_t d1 = (uint32_t)(r1 * PITCH + f1) * 2;

    float acc[2][8][4];
    #pragma unroll
    for (int mt = 0; mt < 2; mt++)
        #pragma unroll
        for (int nt = 0; nt < 8; nt++)
            #pragma unroll
            for (int q = 0; q < 4; q++) acc[mt][nt][q] = 0.0f;

    // ldmatrix lane addressing
    const uint32_t aoff = (uint32_t)((warp_m * 32 + (lane & 15)) * PITCH + (lane >> 4) * 8) * 2;
    const uint32_t boff = (uint32_t)((warp_n * 64 + (lane & 15)) * PITCH + (lane >> 4) * 8) * 2;

    auto load_stage = [&](int s, int kt) {
        uint32_t b = smb + s * STG_B;
        CP16(b + 0 * MAT_B + d0, sA0h + kt);
        CP16(b + 1 * MAT_B + d0, sA0l + kt);
        CP16(b + 2 * MAT_B + d0, sB0h + kt);
        CP16(b + 3 * MAT_B + d0, sB0l + kt);
        CP16(b + 0 * MAT_B + d1, sA1h + kt);
        CP16(b + 1 * MAT_B + d1, sA1l + kt);
        CP16(b + 2 * MAT_B + d1, sB1h + kt);
        CP16(b + 3 * MAT_B + d1, sB1l + kt);
    };

    load_stage(0, 0);
    CP_COMMIT();

    for (int c = 0; c < NITER; c++) {
        if (c + 1 < NITER) {
            load_stage((c + 1) & 1, (c + 1) * 32);
            CP_COMMIT();
            CP_WAIT(1);
        } else {
            CP_WAIT(0);
        }
        __syncthreads();

        const uint32_t sb = smb + (c & 1) * STG_B;
        #pragma unroll
        for (int ks = 0; ks < 2; ks++) {
            const uint32_t ko = ks * 32;  // 16 elts * 2B
            uint32_t aH[2][4], aL[2][4], bH4[4][4], bL4[4][4];
            #pragma unroll
            for (int mt = 0; mt < 2; mt++) {
                ldsm_x4(aH[mt], sb + 0 * MAT_B + aoff + mt * (16 * PITCH * 2) + ko);
                ldsm_x4(aL[mt], sb + 1 * MAT_B + aoff + mt * (16 * PITCH * 2) + ko);
            }
            #pragma unroll
            for (int nt2 = 0; nt2 < 4; nt2++) {
                ldsm_x4(bH4[nt2], sb + 2 * MAT_B + boff + nt2 * (16 * PITCH * 2) + ko);
                ldsm_x4(bL4[nt2], sb + 3 * MAT_B + boff + nt2 * (16 * PITCH * 2) + ko);
            }
            // pass 1: Ah * Bh
            #pragma unroll
            for (int mt = 0; mt < 2; mt++)
                #pragma unroll
                for (int nt = 0; nt < 8; nt++)
                    mma16816(acc[mt][nt], aH[mt], bH4[nt >> 1][nt & 1], bH4[nt >> 1][2 + (nt & 1)]);
            // pass 2: Al * Bh
            #pragma unroll
            for (int mt = 0; mt < 2; mt++)
                #pragma unroll
                for (int nt = 0; nt < 8; nt++)
                    mma16816(acc[mt][nt], aL[mt], bH4[nt >> 1][nt & 1], bH4[nt >> 1][2 + (nt & 1)]);
            // pass 3: Ah * Bl
            #pragma unroll
            for (int mt = 0; mt < 2; mt++)
                #pragma unroll
                for (int nt = 0; nt < 8; nt++)
                    mma16816(acc[mt][nt], aH[mt], bL4[nt >> 1][nt & 1], bL4[nt >> 1][2 + (nt & 1)]);
        }
        __syncthreads();
    }

    // ---- epilogue ----
    float* __restrict__ Cbase = TO_GH ? (float*)g_H : Cout;
    const int colb = nb * 128 + warp_n * 64 + (lane & 3) * 2;
    const float* bp = bias + (size_t)l * Ntot + colb;
    #pragma unroll
    for (int mt = 0; mt < 2; mt++) {
        #pragma unroll
        for (int half = 0; half < 2; half++) {
            int rl = warp_m * 32 + mt * 16 + (lane >> 2) + half * 8;
            int grow = s_rows[rl];
            float* dst = Cbase + ((size_t)l * TT + grow) * Ntot + colb;
            #pragma unroll
            for (int nt = 0; nt < 8; nt++) {
                float vx = acc[mt][nt][half * 2 + 0] + bp[nt * 8];
                float vy = acc[mt][nt][half * 2 + 1] + bp[nt * 8 + 1];
                if (RELU) { vx = fmaxf(vx, 0.f); vy = fmaxf(vy, 0.f); }
                *(float2*)(dst + nt * 8) = make_float2(vx, vy);
            }
        }
    }
}

// =====================================================================
// logits + sigmoid (one warp per token, reads g_H)
// =====================================================================
__global__ void logits_kernel(const float* __restrict__ W_r2,
                              const float* __restrict__ b_r2) {
    int gw   = (blockIdx.x * blockDim.x + threadIdx.x) >> 5;
    int lane = threadIdx.x & 31;
    if (gw >= LL * TT) return;
    int l = gw >> 11;
    const float* h = g_H + (size_t)gw * RR;
    const float* w = W_r2 + l * RR;
    float s = 0.0f;
    #pragma unroll
    for (int r = lane; r < RR; r += 32) s += h[r] * w[r];
    #pragma unroll
    for (int o = 16; o; o >>= 1) s += __shfl_xor_sync(0xFFFFFFFFu, s, o);
    if (lane == 0) {
        float x = s + b_r2[l];
        g_probs[gw] = 1.0f / (1.0f + expf(-x));
    }
}

// =====================================================================
// exact rank on (approx) probs -> compaction + boundary window capture
// =====================================================================
__global__ void rank_kernel() {
    __shared__ float sp[TT];
    int l = blockIdx.x;
    for (int t = threadIdx.x; t < TT; t += blockDim.x) sp[t] = g_probs[l * TT + t];
    __syncthreads();
    for (int t = threadIdx.x; t < TT; t += blockDim.x) {
        float pt = sp[t];
        int rank = 0;
        for (int s = 0; s < TT; s++) {
            float ps = sp[s];
            rank += (ps > pt) || (ps == pt && s < t);
        }
        if (rank < KCAP) g_sel[l * KCAP + rank] = t;
        else             g_idx0[l * KCAP + (rank - KCAP)] = t;
        if (rank >= KCAP - HW && rank < KCAP + HW)
            g_bnd[l * WIN + (rank - (KCAP - HW))] = t;
    }
}

// =====================================================================
// exact fp32 recompute of the 32 boundary tokens; re-rank the window.
// one block per layer, 1024 threads (32 warps = 32 tokens)
// =====================================================================
__global__ void fixup_kernel(const float* __restrict__ hidden,
                             const float* __restrict__ W_r1,
                             const float* __restrict__ b_r1,
                             const float* __restrict__ W_r2,
                             const float* __restrict__ b_r2) {
    __shared__ float win_p[WIN];
    __shared__ int   win_t[WIN];
    int l = blockIdx.x, wid = threadIdx.x >> 5, lane = threadIdx.x & 31;
    int t = g_bnd[l * WIN + wid];
    const float* hrow = hidden + ((size_t)l * TT + t) * DD;
    const float* W1 = W_r1 + (size_t)l * DD * RR;
    float a0 = 0, a1 = 0, a2 = 0, a3 = 0;
    for (int k = 0; k < DD; k++) {
        float hv = hrow[k];
        const float* wr = W1 + (size_t)k * RR + lane;
        a0 = fmaf(hv, wr[0],  a0);
        a1 = fmaf(hv, wr[32], a1);
        a2 = fmaf(hv, wr[64], a2);
        a3 = fmaf(hv, wr[96], a3);
    }
    const float* b1 = b_r1 + l * RR + lane;
    const float* w2 = W_r2 + l * RR + lane;
    float s = fmaxf(a0 + b1[0],  0.f) * w2[0]
            + fmaxf(a1 + b1[32], 0.f) * w2[32]
            + fmaxf(a2 + b1[64], 0.f) * w2[64]
            + fmaxf(a3 + b1[96], 0.f) * w2[96];
    #pragma unroll
    for (int o = 16; o; o >>= 1) s += __shfl_xor_sync(0xFFFFFFFFu, s, o);
    if (lane == 0) {
        float x = s + b_r2[l];
        win_p[wid] = 1.0f / (1.0f + expf(-x));
        win_t[wid] = t;
    }
    __syncthreads();
    if (threadIdx.x < WIN) {
        float pt = win_p[threadIdx.x];
        int   tt = win_t[threadIdx.x];
        int r = 0;
        #pragma unroll
        for (int s2i = 0; s2i < WIN; s2i++) {
            float ps = win_p[s2i];
            int ts = win_t[s2i];
            r += (ps > pt) || (ps == pt && ts < tt);
        }
        if (r < HW) g_sel[l * KCAP + (KCAP - HW) + r] = tt;
        else        g_idx0[l * KCAP + (r - HW)] = tt;
    }
}

// =====================================================================
// selected rows: out = ((1-p)+p) * s2
// =====================================================================
__global__ void copy_sel_kernel(const float* __restrict__ s2,
                                float* __restrict__ out) {
    int b = blockIdx.x;
    int l = b >> 10;
    int t = g_sel[b];
    float p = g_probs[l * TT + t];
    float m = (1.0f - p) + p;
    size_t off = ((size_t)l * TT + t) * DD;
    const float4* src = (const float4*)(s2 + off);
    float4*       dst = (float4*)(out + off);
    #pragma unroll
    for (int i = threadIdx.x; i < DD / 4; i += 256) {
        float4 v = src[i];
        dst[i] = make_float4(m * v.x, m * v.y, m * v.z, m * v.w);
    }
}

// =====================================================================
extern "C" void kernel_launch(void* const* d_in, const int* in_sizes, int n_in,
                              void* d_out, int out_size) {
    const float* hidden = (const float*)d_in[0];
    const float* s2     = (const float*)d_in[1];
    const float* W_r1   = (const float*)d_in[2];
    const float* b_r1   = (const float*)d_in[3];
    const float* W_r2   = (const float*)d_in[4];
    const float* b_r2   = (const float*)d_in[5];
    const float* W_s1   = (const float*)d_in[6];
    const float* b_s1   = (const float*)d_in[7];
    float* out = (float*)d_out;

    const int SMEM = 2 * STG_B;  // 81920
    cudaFuncSetAttribute(hmma_gemm_kernel<true,  false, false>,
                         cudaFuncAttributeMaxDynamicSharedMemorySize, SMEM);
    cudaFuncSetAttribute(hmma_gemm_kernel<false, true, true>,
                         cudaFuncAttributeMaxDynamicSharedMemorySize, SMEM);

    // precompute bf16 splits
    split_hidden_kernel<<<32768, 512>>>((const float4*)hidden);
    transpose_split_kernel<false><<<dim3(64, 4, 16),  dim3(32, 8)>>>(W_r1, DD, RR);
    transpose_split_kernel<true ><<<dim3(64, 64, 16), dim3(32, 8)>>>(W_s1, DD, DD);

    // router: H = relu(hidden @ W_r1 + b) -> g_H (written device-side via TO_GH)
    hmma_gemm_kernel<false, true, true><<<dim3(16, 1, LL), 256, SMEM>>>(
        b_r1, nullptr, RR);
    logits_kernel<<<(LL * TT * 32) / 256, 256>>>(W_r2, b_r2);
    rank_kernel<<<LL, 1024>>>();
    fixup_kernel<<<LL, 1024>>>(hidden, W_r1, b_r1, W_r2, b_r2);
    copy_sel_kernel<<<LL * KCAP, 256>>>(s2, out);

    // s1 GEMM on unselected rows, tensor path
    hmma_gemm_kernel<true, false, false><<<dim3(8, 16, LL), 256, SMEM>>>(
        b_s1, out, DD);
}

// round 5
// speedup vs baseline: 1.5526x; 1.0798x over previous
#include <cuda_runtime.h>
#include <cuda_bf16.h>
#include <math.h>
#include <stdint.h>

// Problem dims
#define LL 16
#define TT 2048
#define DD 2048
#define RR 128
#define KCAP 1024
#define WIN 32          // boundary fixup window
#define HW (WIN / 2)

// ---------------- scratch (device globals) ----------------
__device__ float g_H[(size_t)LL * TT * RR];
__device__ float g_probs[LL * TT];
__device__ int   g_sel [LL * KCAP];
__device__ int   g_idx0[LL * KCAP];
__device__ int   g_bnd [LL * WIN];
// bf16 split copies, hi/lo interleaved per row: [row][hi: D][lo: D]
__device__ __nv_bfloat16 g_A   [(size_t)LL * TT * 2 * DD];
__device__ __nv_bfloat16 g_Ws1t[(size_t)LL * DD * 2 * DD];   // W_s1^T rows
__device__ __nv_bfloat16 g_Wr1t[(size_t)LL * RR * 2 * DD];   // W_r1^T rows

// ---------------- PTX helpers (baseline ISA only) ----------------
__device__ __forceinline__ uint32_t smem_u32(const void* p) {
    uint32_t a;
    asm("{ .reg .u64 t; cvta.to.shared.u64 t, %1; cvt.u32.u64 %0, t; }" : "=r"(a) : "l"(p));
    return a;
}
#define CP16(dst, src) \
    asm volatile("cp.async.cg.shared.global [%0], [%1], 16;" :: "r"(dst), "l"(src))
#define CP_COMMIT() asm volatile("cp.async.commit_group;")
#define CP_WAIT(n)  asm volatile("cp.async.wait_group %0;" :: "n"(n))

__device__ __forceinline__ void ldsm_x4(uint32_t* r, uint32_t addr) {
    asm volatile("ldmatrix.sync.aligned.m8n8.x4.shared.b16 {%0,%1,%2,%3}, [%4];"
                 : "=r"(r[0]), "=r"(r[1]), "=r"(r[2]), "=r"(r[3]) : "r"(addr));
}
__device__ __forceinline__ void mma16816(float* d, const uint32_t* a,
                                         uint32_t b0, uint32_t b1) {
    asm volatile(
        "mma.sync.aligned.m16n8k16.row.col.f32.bf16.bf16.f32 "
        "{%0,%1,%2,%3}, {%4,%5,%6,%7}, {%8,%9}, {%0,%1,%2,%3};"
        : "+f"(d[0]), "+f"(d[1]), "+f"(d[2]), "+f"(d[3])
        : "r"(a[0]), "r"(a[1]), "r"(a[2]), "r"(a[3]), "r"(b0), "r"(b1));
}

// bf16 hi/lo split of two floats, packed (y<<16)|x
__device__ __forceinline__ void split2(float x, float y, uint32_t& hi, uint32_t& lo) {
    __nv_bfloat16 hx = __float2bfloat16(x);
    __nv_bfloat16 hy = __float2bfloat16(y);
    __nv_bfloat16 lx = __float2bfloat16(x - __bfloat162float(hx));
    __nv_bfloat16 ly = __float2bfloat16(y - __bfloat162float(hy));
    hi = ((uint32_t)__bfloat16_as_ushort(hy) << 16) | __bfloat16_as_ushort(hx);
    lo = ((uint32_t)__bfloat16_as_ushort(ly) << 16) | __bfloat16_as_ushort(lx);
}

// =====================================================================
// hidden f32 -> g_A (hi/lo interleaved per row)
// =====================================================================
__global__ void split_hidden_kernel(const float4* __restrict__ h) {
    size_t i = (size_t)blockIdx.x * blockDim.x + threadIdx.x;   // < L*T*D/4
    float4 v = h[i];
    uint32_t h01, l01, h23, l23;
    split2(v.x, v.y, h01, l01);
    split2(v.z, v.w, h23, l23);
    size_t row = i >> 9;           // DD/4 = 512 float4 per row
    size_t c4  = i & 511;
    uint2* base = (uint2*)(g_A + row * 2 * DD);
    base[c4]       = make_uint2(h01, h23);
    base[c4 + 512] = make_uint2(l01, l23);
}

// =====================================================================
// W[l,k,n] f32 -> Wt[l,n][hi D | lo D] bf16
// =====================================================================
template<bool S1>
__global__ void transpose_split_kernel(const float* __restrict__ W, int K, int N) {
    __shared__ float tile[32][33];
    const int l  = blockIdx.z;
    const int k0 = blockIdx.x * 32;
    const int n0 = blockIdx.y * 32;
    const int tx = threadIdx.x, ty = threadIdx.y;
    const float* Wl = W + (size_t)l * K * N;
    #pragma unroll
    for (int r = 0; r < 4; r++)
        tile[ty + r * 8][tx] = Wl[(size_t)(k0 + ty + r * 8) * N + n0 + tx];
    __syncthreads();
    __nv_bfloat16* Wt = S1 ? g_Ws1t : g_Wr1t;
    #pragma unroll
    for (int r = 0; r < 4; r++) {
        int n = n0 + ty + r * 8;
        float v = tile[tx][ty + r * 8];
        __nv_bfloat16 h = __float2bfloat16(v);
        __nv_bfloat16 lo = __float2bfloat16(v - __bfloat162float(h));
        size_t o = ((size_t)l * N + n) * 2 * DD + k0 + tx;
        Wt[o]      = h;
        Wt[o + DD] = lo;
    }
}

// =====================================================================
// HMMA GEMM: C[128 x 128 tile] = A(bf16 hi/lo) @ B^T(bf16 hi/lo), 3-term split.
// grid (mtiles, Ntot/128, L), 256 threads (warps 4x2), BK=32, 2-stage cp.async.
// __launch_bounds__(256, 2): keep <=128 regs for 2 CTAs/SM.
// =====================================================================
#define PITCH 40                    // bf16 elts per smem row (32 + 8 pad)
#define MAT_ELT (128 * PITCH)       // 5120 elts per matrix
#define MAT_B   (MAT_ELT * 2)       // 10240 bytes
#define STG_B   (4 * MAT_B)         // Ah,Al,Bh,Bl : 40960 bytes
#define NITER   (DD / 32)           // 64

template<bool GATHER, bool RELU, bool TO_GH>
__global__ __launch_bounds__(256, 2)
void hmma_gemm_kernel(const float* __restrict__ bias,
                      float* __restrict__ Cout, int Ntot) {
    extern __shared__ __align__(16) char smraw[];
    const uint32_t smb = smem_u32(smraw);

    const int tid  = threadIdx.x;
    const int lane = tid & 31;
    const int wid  = tid >> 5;
    const int warp_m = wid & 3;     // 4 warps over M (32 rows each)
    const int warp_n = wid >> 2;    // 2 warps over N (64 cols each)
    const int mb = blockIdx.x, nb = blockIdx.y, l = blockIdx.z;

    __shared__ int s_rows[128];
    if (tid < 128)
        s_rows[tid] = GATHER ? g_idx0[l * KCAP + mb * 128 + tid] : (mb * 128 + tid);
    __syncthreads();

    // cp.async assignment: 512 chunks of 16B per matrix; this thread owns c0,c1
    const int c0 = tid, c1 = tid + 256;
    const int r0 = c0 >> 2, r1 = c1 >> 2;
    const int f0 = (c0 & 3) * 8, f1 = (c1 & 3) * 8;        // elt col
    const __nv_bfloat16* __restrict__ Aall = g_A + (size_t)l * TT * 2 * DD;
    const __nv_bfloat16* __restrict__ Wt =
        (GATHER ? g_Ws1t : g_Wr1t) + ((size_t)l * Ntot + nb * 128) * 2 * DD;
    const __nv_bfloat16* aPtr0 = Aall + (size_t)s_rows[r0] * 2 * DD + f0;
    const __nv_bfloat16* aPtr1 = Aall + (size_t)s_rows[r1] * 2 * DD + f1;
    const __nv_bfloat16* bPtr0 = Wt + (size_t)r0 * 2 * DD + f0;
    const __nv_bfloat16* bPtr1 = Wt + (size_t)r1 * 2 * DD + f1;
    const uint32_t d0 = (uint32_t)(r0 * PITCH + f0) * 2;
    const uint32_t d1 = (uint32_t)(r1 * PITCH + f1) * 2;

    float acc[2][8][4];
    #pragma unroll
    for (int mt = 0; mt < 2; mt++)
        #pragma unroll
        for (int nt = 0; nt < 8; nt++)
            #pragma unroll
            for (int q = 0; q < 4; q++) acc[mt][nt][q] = 0.0f;

    // ldmatrix lane addressing (hardware-verified mapping; do not change)
    const uint32_t aoff = (uint32_t)((warp_m * 32 + (lane & 15)) * PITCH + (lane >> 4) * 8) * 2;
    const uint32_t boff = (uint32_t)((warp_n * 64 + (lane & 15)) * PITCH + (lane >> 4) * 8) * 2;

    auto load_stage = [&](int s, int kt) {
        uint32_t b = smb + s * STG_B;
        CP16(b + 0 * MAT_B + d0, aPtr0 + kt);
        CP16(b + 1 * MAT_B + d0, aPtr0 + kt + DD);
        CP16(b + 2 * MAT_B + d0, bPtr0 + kt);
        CP16(b + 3 * MAT_B + d0, bPtr0 + kt + DD);
        CP16(b + 0 * MAT_B + d1, aPtr1 + kt);
        CP16(b + 1 * MAT_B + d1, aPtr1 + kt + DD);
        CP16(b + 2 * MAT_B + d1, bPtr1 + kt);
        CP16(b + 3 * MAT_B + d1, bPtr1 + kt + DD);
    };

    load_stage(0, 0);
    CP_COMMIT();

    for (int c = 0; c < NITER; c++) {
        if (c + 1 < NITER) {
            load_stage((c + 1) & 1, (c + 1) * 32);
            CP_COMMIT();
            CP_WAIT(1);
        } else {
            CP_WAIT(0);
        }
        __syncthreads();

        const uint32_t sb = smb + (c & 1) * STG_B;
        #pragma unroll
        for (int ks = 0; ks < 2; ks++) {
            const uint32_t ko = ks * 32;  // 16 elts * 2B
            uint32_t aH[2][4], aL[2][4], bfr[4][4];
            #pragma unroll
            for (int mt = 0; mt < 2; mt++) {
                ldsm_x4(aH[mt], sb + 0 * MAT_B + aoff + mt * (16 * PITCH * 2) + ko);
                ldsm_x4(aL[mt], sb + 1 * MAT_B + aoff + mt * (16 * PITCH * 2) + ko);
            }
            // Bh fragments -> pass 1 (Ah*Bh) and pass 2 (Al*Bh)
            #pragma unroll
            for (int n4 = 0; n4 < 4; n4++)
                ldsm_x4(bfr[n4], sb + 2 * MAT_B + boff + n4 * (16 * PITCH * 2) + ko);
            #pragma unroll
            for (int mt = 0; mt < 2; mt++)
                #pragma unroll
                for (int nt = 0; nt < 8; nt++)
                    mma16816(acc[mt][nt], aH[mt], bfr[nt >> 1][nt & 1], bfr[nt >> 1][2 + (nt & 1)]);
            #pragma unroll
            for (int mt = 0; mt < 2; mt++)
                #pragma unroll
                for (int nt = 0; nt < 8; nt++)
                    mma16816(acc[mt][nt], aL[mt], bfr[nt >> 1][nt & 1], bfr[nt >> 1][2 + (nt & 1)]);
            // Bl fragments (reuse regs) -> pass 3 (Ah*Bl)
            #pragma unroll
            for (int n4 = 0; n4 < 4; n4++)
                ldsm_x4(bfr[n4], sb + 3 * MAT_B + boff + n4 * (16 * PITCH * 2) + ko);
            #pragma unroll
            for (int mt = 0; mt < 2; mt++)
                #pragma unroll
                for (int nt = 0; nt < 8; nt++)
                    mma16816(acc[mt][nt], aH[mt], bfr[nt >> 1][nt & 1], bfr[nt >> 1][2 + (nt & 1)]);
        }
        __syncthreads();
    }

    // ---- epilogue ----
    float* __restrict__ Cbase = TO_GH ? (float*)g_H : Cout;
    const int colb = nb * 128 + warp_n * 64 + (lane & 3) * 2;
    const float* bp = bias + (size_t)l * Ntot + colb;
    #pragma unroll
    for (int mt = 0; mt < 2; mt++) {
        #pragma unroll
        for (int half = 0; half < 2; half++) {
            int rl = warp_m * 32 + mt * 16 + (lane >> 2) + half * 8;
            int grow = s_rows[rl];
            float* dst = Cbase + ((size_t)l * TT + grow) * Ntot + colb;
            #pragma unroll
            for (int nt = 0; nt < 8; nt++) {
                float vx = acc[mt][nt][half * 2 + 0] + bp[nt * 8];
                float vy = acc[mt][nt][half * 2 + 1] + bp[nt * 8 + 1];
                if (RELU) { vx = fmaxf(vx, 0.f); vy = fmaxf(vy, 0.f); }
                *(float2*)(dst + nt * 8) = make_float2(vx, vy);
            }
        }
    }
}

// =====================================================================
// logits + sigmoid (one warp per token, reads g_H)
// =====================================================================
__global__ void logits_kernel(const float* __restrict__ W_r2,
                              const float* __restrict__ b_r2) {
    int gw   = (blockIdx.x * blockDim.x + threadIdx.x) >> 5;
    int lane = threadIdx.x & 31;
    if (gw >= LL * TT) return;
    int l = gw >> 11;
    const float* h = g_H + (size_t)gw * RR;
    const float* w = W_r2 + l * RR;
    float s = 0.0f;
    #pragma unroll
    for (int r = lane; r < RR; r += 32) s += h[r] * w[r];
    #pragma unroll
    for (int o = 16; o; o >>= 1) s += __shfl_xor_sync(0xFFFFFFFFu, s, o);
    if (lane == 0) {
        float x = s + b_r2[l];
        g_probs[gw] = 1.0f / (1.0f + expf(-x));
    }
}

// =====================================================================
// exact rank on (approx) probs -> compaction + boundary window capture
// =====================================================================
__global__ void rank_kernel() {
    __shared__ float sp[TT];
    int l = blockIdx.x;
    for (int t = threadIdx.x; t < TT; t += blockDim.x) sp[t] = g_probs[l * TT + t];
    __syncthreads();
    for (int t = threadIdx.x; t < TT; t += blockDim.x) {
        float pt = sp[t];
        int rank = 0;
        for (int s = 0; s < TT; s++) {
            float ps = sp[s];
            rank += (ps > pt) || (ps == pt && s < t);
        }
        if (rank < KCAP) g_sel[l * KCAP + rank] = t;
        else             g_idx0[l * KCAP + (rank - KCAP)] = t;
        if (rank >= KCAP - HW && rank < KCAP + HW)
            g_bnd[l * WIN + (rank - (KCAP - HW))] = t;
    }
}

// =====================================================================
// exact fp32 recompute of the 32 boundary tokens; re-rank the window.
// =====================================================================
__global__ void fixup_kernel(const float* __restrict__ hidden,
                             const float* __restrict__ W_r1,
                             const float* __restrict__ b_r1,
                             const float* __restrict__ W_r2,
                             const float* __restrict__ b_r2) {
    __shared__ float win_p[WIN];
    __shared__ int   win_t[WIN];
    int l = blockIdx.x, wid = threadIdx.x >> 5, lane = threadIdx.x & 31;
    int t = g_bnd[l * WIN + wid];
    const float* hrow = hidden + ((size_t)l * TT + t) * DD;
    const float* W1 = W_r1 + (size_t)l * DD * RR;
    float a0 = 0, a1 = 0, a2 = 0, a3 = 0;
    for (int k = 0; k < DD; k++) {
        float hv = hrow[k];
        const float* wr = W1 + (size_t)k * RR + lane;
        a0 = fmaf(hv, wr[0],  a0);
        a1 = fmaf(hv, wr[32], a1);
        a2 = fmaf(hv, wr[64], a2);
        a3 = fmaf(hv, wr[96], a3);
    }
    const float* b1 = b_r1 + l * RR + lane;
    const float* w2 = W_r2 + l * RR + lane;
    float s = fmaxf(a0 + b1[0],  0.f) * w2[0]
            + fmaxf(a1 + b1[32], 0.f) * w2[32]
            + fmaxf(a2 + b1[64], 0.f) * w2[64]
            + fmaxf(a3 + b1[96], 0.f) * w2[96];
    #pragma unroll
    for (int o = 16; o; o >>= 1) s += __shfl_xor_sync(0xFFFFFFFFu, s, o);
    if (lane == 0) {
        float x = s + b_r2[l];
        win_p[wid] = 1.0f / (1.0f + expf(-x));
        win_t[wid] = t;
    }
    __syncthreads();
    if (threadIdx.x < WIN) {
        float pt = win_p[threadIdx.x];
        int   tt = win_t[threadIdx.x];
        int r = 0;
        #pragma unroll
        for (int s2i = 0; s2i < WIN; s2i++) {
            float ps = win_p[s2i];
            int ts = win_t[s2i];
            r += (ps > pt) || (ps == pt && ts < tt);
        }
        if (r < HW) g_sel[l * KCAP + (KCAP - HW) + r] = tt;
        else        g_idx0[l * KCAP + (r - HW)] = tt;
    }
}

// =====================================================================
// selected rows: out = ((1-p)+p) * s2
// =====================================================================
__global__ void copy_sel_kernel(const float* __restrict__ s2,
                                float* __restrict__ out) {
    int b = blockIdx.x;
    int l = b >> 10;
    int t = g_sel[b];
    float p = g_probs[l * TT + t];
    float m = (1.0f - p) + p;
    size_t off = ((size_t)l * TT + t) * DD;
    const float4* src = (const float4*)(s2 + off);
    float4*       dst = (float4*)(out + off);
    #pragma unroll
    for (int i = threadIdx.x; i < DD / 4; i += 256) {
        float4 v = src[i];
        dst[i] = make_float4(m * v.x, m * v.y, m * v.z, m * v.w);
    }
}

// =====================================================================
extern "C" void kernel_launch(void* const* d_in, const int* in_sizes, int n_in,
                              void* d_out, int out_size) {
    const float* hidden = (const float*)d_in[0];
    const float* s2     = (const float*)d_in[1];
    const float* W_r1   = (const float*)d_in[2];
    const float* b_r1   = (const float*)d_in[3];
    const float* W_r2   = (const float*)d_in[4];
    const float* b_r2   = (const float*)d_in[5];
    const float* W_s1   = (const float*)d_in[6];
    const float* b_s1   = (const float*)d_in[7];
    float* out = (float*)d_out;

    const int SMEM = 2 * STG_B;  // 81920
    cudaFuncSetAttribute(hmma_gemm_kernel<true,  false, false>,
                         cudaFuncAttributeMaxDynamicSharedMemorySize, SMEM);
    cudaFuncSetAttribute(hmma_gemm_kernel<false, true, true>,
                         cudaFuncAttributeMaxDynamicSharedMemorySize, SMEM);

    // precompute bf16 splits
    split_hidden_kernel<<<32768, 512>>>((const float4*)hidden);
    transpose_split_kernel<false><<<dim3(64, 4, 16),  dim3(32, 8)>>>(W_r1, DD, RR);
    transpose_split_kernel<true ><<<dim3(64, 64, 16), dim3(32, 8)>>>(W_s1, DD, DD);

    // router: H = relu(hidden @ W_r1 + b) -> g_H (device-side store)
    hmma_gemm_kernel<false, true, true><<<dim3(16, 1, LL), 256, SMEM>>>(
        b_r1, nullptr, RR);
    logits_kernel<<<(LL * TT * 32) / 256, 256>>>(W_r2, b_r2);
    rank_kernel<<<LL, 1024>>>();
    fixup_kernel<<<LL, 1024>>>(hidden, W_r1, b_r1, W_r2, b_r2);
    copy_sel_kernel<<<LL * KCAP, 256>>>(s2, out);

    // s1 GEMM on unselected rows, tensor path
    hmma_gemm_kernel<true, false, false><<<dim3(8, 16, LL), 256, SMEM>>>(
        b_s1, out, DD);
}